// round 10
// baseline (speedup 1.0000x reference)
#include <cuda_runtime.h>

// LFQ quantizer — sparse factorized softmax, ONE kernel, ONE 8-CTA cluster.
// N = 8192 samples, D = 14, K = 16384, T = 0.01.
//
// softmax factorizes: p_j = prod_d sigmoid(400 x_d c_jd).
// u_d = e^{-400|x_d|} > 1e-4 only for |x_d| < 0.023 (~1.8%/dim) -> each
// sample's mass lives on ~1.3 codes: enumerate subsets of the soft-dim mask
// (dropped flip mass ~3e-6/sample -> entropy error ~3e-5 abs, well in tol).
// sample_entropy = sum_d binary_entropy(sigmoid(400 x_d)) (factorized).
//
// 8 CTAs x 1024 threads = 8192 threads = 1 thread/sample, launched as a single
// cluster. Grid-wide sync = barrier.cluster (~400 cyc HW) instead of L2
// atomic+poll (several thousand cycles). No global counters at all -> nothing
// to reset; graph-replay safe by construction (g_M re-zeroed in phase 2).

#define DIMS 14
#define NCODES 16384
#define NB 8
#define BTH 1024
#define EPB (BTH * DIMS)       // 14336 floats per block
#define E4PB (EPB / 4)         // 3584 float4 per block
#define CPB (NCODES / NB)      // 2048 codes per block in phase 2
#define UTH 1e-4f
#define SMEM_BYTES (EPB * 4)   // 57344 B dynamic smem

__device__ float g_M[NCODES];                  // per-code prob sums (zeroed each run)
__device__ float g_cP[NB], g_hP[NB], g_eP[NB]; // per-block partial slots

#define CLUSTER_SYNC() do { \
    asm volatile("barrier.cluster.arrive.aligned;" ::: "memory"); \
    asm volatile("barrier.cluster.wait.aligned;" ::: "memory"); \
} while (0)

__global__ void __launch_bounds__(BTH, 1) __cluster_dims__(NB, 1, 1)
lfq_fused(const float* __restrict__ x, float* __restrict__ out,
          int qn, int out_size, float inv_n) {
    extern __shared__ unsigned us[];   // bit31 = quantized bit, bits30..0 = u
    __shared__ float w1[32], w2[32];

    const int tid = threadIdx.x;
    const int lane = tid & 31, wid = tid >> 5;
    const int bid = blockIdx.x;        // == cluster rank (single cluster)
    const float4* x4 = (const float4*)x + bid * E4PB;
    float4* o4 = (float4*)out + bid * E4PB;

    // ========== phase 1a: elementwise, fully coalesced float4 ==========
    float commit = 0.f, h = 0.f;
    #pragma unroll
    for (int k = 0; k < 4; ++k) {
        int i = tid + k * BTH;
        if (i < E4PB) {
            float4 xv = x4[i];
            float vx[4] = {xv.x, xv.y, xv.z, xv.w};
            float qq[4];
            #pragma unroll
            for (int j = 0; j < 4; ++j) {
                float v = vx[j];
                bool pos = (v > 0.f);
                float qz = pos ? 1.f : -1.f;
                qq[j] = qz;
                float dq = v - qz;
                commit += dq * dq;
                float t = fabsf(400.f * v);
                float u = __expf(-t);                    // flip ratio e^{-|z|}
                float inv = 1.f / (1.f + u);
                h += (u > 1e-4f) ? (__logf(1.f + u) + t * u * inv)
                                 : u * (1.f + t);        // 1st order, err ~ u^2
                us[4 * i + j] = __float_as_uint(u) | (pos ? 0x80000000u : 0u);
            }
            float4 q; q.x = qq[0]; q.y = qq[1]; q.z = qq[2]; q.w = qq[3];
            o4[i] = q;                                   // coalesced STG.128
        }
    }
    __syncthreads();

    // ========== phase 1b: per-sample sparse scatter (1 thread/sample) ==========
    {
        const unsigned* up = &us[tid * DIMS];
        float p_main = 1.f;
        int j_main = 0;
        unsigned soft = 0;
        #pragma unroll
        for (int d = 0; d < DIMS; ++d) {
            unsigned w = up[d];
            float u = __uint_as_float(w & 0x7fffffffu);
            if (w >> 31) j_main |= (1 << d);
            p_main *= 1.f / (1.f + u);                   // exact normalization
            if (u > UTH) soft |= (1u << d);              // enumerate only these
        }
        unsigned m = 0;
        do {                                             // subsets of `soft`
            float p = p_main;
            unsigned r = m;
            while (r) {
                int d = __ffs(r) - 1;
                p *= __uint_as_float(up[d] & 0x7fffffffu);
                r &= r - 1;
            }
            atomicAdd(&g_M[j_main ^ (int)m], p);
            m = (m - soft) & soft;
        } while (m);
    }

    // block-reduce commit & sample-entropy (32 warps)
    #pragma unroll
    for (int off = 16; off; off >>= 1) {
        commit += __shfl_down_sync(0xffffffffu, commit, off);
        h      += __shfl_down_sync(0xffffffffu, h, off);
    }
    if (lane == 0) { w1[wid] = commit; w2[wid] = h; }
    __syncthreads();
    if (wid == 0) {                                      // sum 32 warp partials
        float cs = w1[lane], hs = w2[lane];
        #pragma unroll
        for (int off = 16; off; off >>= 1) {
            cs += __shfl_down_sync(0xffffffffu, cs, off);
            hs += __shfl_down_sync(0xffffffffu, hs, off);
        }
        if (lane == 0) { g_cP[bid] = cs; g_hP[bid] = hs; }
    }

    // ========== grid barrier #1: hardware cluster barrier ==========
    __threadfence();                   // publish g_M atomics + partial STGs
    CLUSTER_SYNC();

    // ========== phase 2: distributed entropy over avg_probs + re-zero ==========
    float ea = 0.f;
    const int base = bid * CPB;
    #pragma unroll
    for (int k = 0; k < CPB / BTH; ++k) {                // 2 iters, coalesced
        int c = base + k * BTH + tid;
        float v = __ldcg(&g_M[c]);
        g_M[c] = 0.f;                                    // reset for next replay
        float mm = v * inv_n;
        ea -= mm * __logf(mm + 1e-5f);                   // mm==0 -> exactly 0
    }
    #pragma unroll
    for (int off = 16; off; off >>= 1)
        ea += __shfl_down_sync(0xffffffffu, ea, off);
    if (lane == 0) w1[wid] = ea;
    __syncthreads();
    if (tid == 0) {
        float es = 0.f;
        #pragma unroll
        for (int w = 0; w < 32; ++w) es += w1[w];
        g_eP[bid] = es;
    }

    // ========== grid barrier #2, then rank 0 finalizes ==========
    __threadfence();                   // publish g_eP
    CLUSTER_SYNC();

    if (bid == 0 && wid == 0) {
        float cs = (lane < NB) ? g_cP[lane] : 0.f;
        float hs = (lane < NB) ? g_hP[lane] : 0.f;
        float es = (lane < NB) ? g_eP[lane] : 0.f;
        #pragma unroll
        for (int off = 4; off; off >>= 1) {
            cs += __shfl_down_sync(0xffffffffu, cs, off);
            hs += __shfl_down_sync(0xffffffffu, hs, off);
            es += __shfl_down_sync(0xffffffffu, es, off);
        }
        if (lane == 0) {
            float samp = hs * inv_n;
            float cm = cs * inv_n * (1.f / (float)DIMS);
            if (out_size >= qn + 4) {
                out[qn + 0] = samp - es;                 // entropy_aux_loss
                out[qn + 1] = samp;                      // sample_entropy
                out[qn + 2] = es;                        // avg_entropy
                out[qn + 3] = cm;                        // commit_loss
            }
        }
    }
}

extern "C" void kernel_launch(void* const* d_in, const int* in_sizes, int n_in,
                              void* d_out, int out_size) {
    const float* x = (const float*)d_in[0];
    float* out = (float*)d_out;
    int qn = in_sizes[0];                   // 8*1024*14 = 114688
    float inv_n = 1.f / (float)(qn / DIMS); // 1/8192

    static bool attr_set = false;           // idempotent attribute, capture-time only
    if (!attr_set) {
        cudaFuncSetAttribute(lfq_fused, cudaFuncAttributeMaxDynamicSharedMemorySize,
                             SMEM_BYTES);
        attr_set = true;
    }
    lfq_fused<<<NB, BTH, SMEM_BYTES>>>(x, out, qn, out_size, inv_n);
}